// round 1
// baseline (speedup 1.0000x reference)
#include <cuda_runtime.h>
#include <cuda_bf16.h>
#include <math.h>

// Top2Router: x[4,4096,2048] fp32, W[8,2048], b[8]
// out (float32, concat): top2_val[16384*2] | top2_idx[16384*2] | gate[16384*8]
//
// Strategy: lane==token broadcast-W GEMV.
//  - 512 blocks x 256 threads, 32 tokens/block.
//  - Wt[k][e] (2048x8) staged once in smem; inner loop reads it at a single
//    address per warp -> bank broadcast (free).
//  - x staged in 8 chunks of 32x256 fp32, row stride 260 floats so that both
//    the coalesced global fill and the lane-major float4 compute reads are
//    bank-conflict-free.
//  - 8 warps split K (32 k each per chunk); partial acc reduced via smem.
//  - 32 threads do softmax + stable top2 (strict > keeps lowest index on tie,
//    matching jax.lax.top_k).

#define NTOK_BLK 32
#define KCHUNK   256
#define XS_STRIDE 260          // 260 % 32 == 4 -> conflict-free float4 access
#define D_MODEL  2048
#define NEXP     8

__global__ __launch_bounds__(256, 2)
void top2_router_kernel(const float* __restrict__ x,
                        const float* __restrict__ W,
                        const float* __restrict__ b,
                        float* __restrict__ out,
                        int n_tok)
{
    extern __shared__ float smem[];
    float* wt  = smem;                          // 2048*8      = 16384 floats
    float* xs  = wt + D_MODEL * NEXP;           // 32*260      = 8320 floats
    float* red = xs + NTOK_BLK * XS_STRIDE;     // 8*32*8      = 2048 floats
    float* lg  = red + 8 * NTOK_BLK * NEXP;     // 32*8        = 256 floats

    const int tid  = threadIdx.x;
    const int w    = tid >> 5;
    const int lane = tid & 31;
    const int tokenBase = blockIdx.x * NTOK_BLK;

    // ---- stage W transposed: wt[k*8+e] = W[e*2048+k]; coalesced global reads
    #pragma unroll
    for (int i = 0; i < 64; ++i) {
        int idx = tid + i * 256;                // 0..16383
        int e = idx >> 11;                      // /2048
        int k = idx & (D_MODEL - 1);
        wt[k * NEXP + e] = W[idx];
    }

    float acc[NEXP];
    #pragma unroll
    for (int e = 0; e < NEXP; ++e) acc[e] = 0.f;

    // ---- K loop: 8 chunks of 256
    for (int c = 0; c < D_MODEL / KCHUNK; ++c) {
        // cooperative tile load: 32 tokens x 256 floats = 2048 float4
        #pragma unroll
        for (int i = 0; i < 8; ++i) {
            int idx = tid + i * 256;            // 0..2047 (float4 units)
            int t   = idx >> 6;                 // 64 float4 per row
            int k4  = idx & 63;
            float4 v = *reinterpret_cast<const float4*>(
                x + (size_t)(tokenBase + t) * D_MODEL + c * KCHUNK + k4 * 4);
            *reinterpret_cast<float4*>(xs + t * XS_STRIDE + k4 * 4) = v;
        }
        __syncthreads();

        // compute: warp w handles k_local in [w*32, w*32+32), lane==token
        const float* xrow = xs + lane * XS_STRIDE + w * 32;
        const float* wrow = wt + (size_t)(c * KCHUNK + w * 32) * NEXP;
        #pragma unroll
        for (int s = 0; s < 8; ++s) {
            float4 xv = *reinterpret_cast<const float4*>(xrow + s * 4);
            #pragma unroll
            for (int j = 0; j < 4; ++j) {
                float xk = (j == 0) ? xv.x : (j == 1) ? xv.y : (j == 2) ? xv.z : xv.w;
                const float* wp = wrow + (size_t)(s * 4 + j) * NEXP;
                float4 w0 = *reinterpret_cast<const float4*>(wp);      // broadcast
                float4 w1 = *reinterpret_cast<const float4*>(wp + 4);  // broadcast
                acc[0] += xk * w0.x;  acc[1] += xk * w0.y;
                acc[2] += xk * w0.z;  acc[3] += xk * w0.w;
                acc[4] += xk * w1.x;  acc[5] += xk * w1.y;
                acc[6] += xk * w1.z;  acc[7] += xk * w1.w;
            }
        }
        __syncthreads();
    }

    // ---- cross-warp reduction: red[w][lane][e]
    #pragma unroll
    for (int e = 0; e < NEXP; ++e)
        red[(w * NTOK_BLK + lane) * NEXP + e] = acc[e];
    __syncthreads();

    // 256 threads: thread i reduces (tok = i/8, e = i%8)
    {
        int tok = tid >> 3;
        int e   = tid & 7;
        float s = 0.f;
        #pragma unroll
        for (int ww = 0; ww < 8; ++ww)
            s += red[(ww * NTOK_BLK + tok) * NEXP + e];
        lg[tok * NEXP + e] = s + b[e];
    }
    __syncthreads();

    // ---- per-token softmax + top2 (threads 0..31)
    if (tid < NTOK_BLK) {
        const int g = tokenBase + tid;
        float gv[NEXP];
        float mx = -INFINITY;
        #pragma unroll
        for (int e = 0; e < NEXP; ++e) {
            gv[e] = lg[tid * NEXP + e];
            mx = fmaxf(mx, gv[e]);
        }
        float ssum = 0.f;
        #pragma unroll
        for (int e = 0; e < NEXP; ++e) {
            gv[e] = __expf(gv[e] - mx);
            ssum += gv[e];
        }
        float inv = 1.f / ssum;
        float* gate_out = out + (size_t)n_tok * 4;   // after val(2N) + idx(2N)
        #pragma unroll
        for (int e = 0; e < NEXP; ++e) {
            gv[e] *= inv;
            gate_out[(size_t)g * NEXP + e] = gv[e];
        }
        // stable top-2 (strict > keeps lowest index on tie)
        int i1 = 0; float v1 = gv[0];
        #pragma unroll
        for (int e = 1; e < NEXP; ++e)
            if (gv[e] > v1) { v1 = gv[e]; i1 = e; }
        int i2 = -1; float v2 = -INFINITY;
        #pragma unroll
        for (int e = 0; e < NEXP; ++e)
            if (e != i1 && gv[e] > v2) { v2 = gv[e]; i2 = e; }

        out[(size_t)g * 2 + 0] = v1;
        out[(size_t)g * 2 + 1] = v2;
        float* idx_out = out + (size_t)n_tok * 2;
        idx_out[(size_t)g * 2 + 0] = (float)i1;
        idx_out[(size_t)g * 2 + 1] = (float)i2;
    }
}

extern "C" void kernel_launch(void* const* d_in, const int* in_sizes, int n_in,
                              void* d_out, int out_size)
{
    const float* x = (const float*)d_in[0];
    const float* W = (const float*)d_in[1];
    const float* b = (const float*)d_in[2];
    float* out = (float*)d_out;

    const int n_tok = in_sizes[0] / D_MODEL;    // 16384
    const int smem_bytes = (D_MODEL * NEXP + NTOK_BLK * XS_STRIDE +
                            8 * NTOK_BLK * NEXP + NTOK_BLK * NEXP) * (int)sizeof(float);

    static bool attr_set = false;
    if (!attr_set) {
        cudaFuncSetAttribute(top2_router_kernel,
                             cudaFuncAttributeMaxDynamicSharedMemorySize, smem_bytes);
        attr_set = true;
    }

    int blocks = n_tok / NTOK_BLK;              // 512
    top2_router_kernel<<<blocks, 256, smem_bytes>>>(x, W, b, out, n_tok);
}

// round 2
// speedup vs baseline: 1.6740x; 1.6740x over previous
#include <cuda_runtime.h>
#include <math.h>

// Top2Router: x[16384,2048] fp32, W[8,2048], b[8]
// out (fp32 concat): top2_val[N*2] | top2_idx[N*2] | gate[N*8]
//
// 128 blocks x 512 threads, 128 tokens/block -> single resident wave.
// lane==token broadcast-W GEMV, cp.async double-buffered x tiles,
// expert-pair packed f32x2 accumulation (FFMA2).

#define D_MODEL   2048
#define NEXP      8
#define NTOK      128                 // tokens per block
#define KCHUNK    128
#define NCHUNK    (D_MODEL / KCHUNK)  // 16
#define XS_STRIDE 132                 // 132 % 32 == 4 -> conflict-free float4 LDS
#define THREADS   512
#define NWARP     16
#define KSLICE    (KCHUNK / NWARP)    // 8 k per warp per chunk

typedef unsigned long long u64;

__device__ __forceinline__ void cp_async16(float* smem_dst, const float* gsrc) {
    unsigned saddr = (unsigned)__cvta_generic_to_shared(smem_dst);
    asm volatile("cp.async.cg.shared.global [%0], [%1], 16;\n"
                 :: "r"(saddr), "l"(gsrc));
}
#define CP_COMMIT() asm volatile("cp.async.commit_group;\n" ::: "memory")
#define CP_WAIT(n)  asm volatile("cp.async.wait_group %0;\n" :: "n"(n) : "memory")

__global__ __launch_bounds__(THREADS, 1)
void top2_router_kernel(const float* __restrict__ x,
                        const float* __restrict__ W,
                        const float* __restrict__ b,
                        float* __restrict__ out,
                        int n_tok)
{
    extern __shared__ float smem[];
    float* wt  = smem;                       // 2048*8 = 16384 floats (64 KB)
    float* xs0 = wt + D_MODEL * NEXP;        // 128*132 = 16896 floats
    float* xs1 = xs0 + NTOK * XS_STRIDE;     // 16896 floats

    const int tid  = threadIdx.x;
    const int w    = tid >> 5;
    const int lane = tid & 31;
    const int tokenBase = blockIdx.x * NTOK;

    // ---- stage W transposed: wt[k*8+e] = W[e*2048+k] (coalesced global reads)
    #pragma unroll
    for (int i = 0; i < (D_MODEL * NEXP) / THREADS; ++i) {   // 32
        int idx = tid + i * THREADS;
        int e = idx >> 11;
        int k = idx & (D_MODEL - 1);
        wt[k * NEXP + e] = W[idx];
    }
    const u64* wt64 = reinterpret_cast<const u64*>(wt);      // pair (e,e+1) per entry

    // ---- f32x2 accumulators: acc[token][expert-pair]
    u64 acc[4][4];
    #pragma unroll
    for (int t = 0; t < 4; ++t)
        #pragma unroll
        for (int p = 0; p < 4; ++p) acc[t][p] = 0ull;

    const float* gx = x + (size_t)tokenBase * D_MODEL;

    // prologue: prefetch chunk 0 into xs0
    {
        #pragma unroll
        for (int i = 0; i < 8; ++i) {
            int idx = tid + i * THREADS;       // 0..4095 (float4 units)
            int t   = idx >> 5;                // 32 float4 per row
            int k4  = idx & 31;
            cp_async16(xs0 + t * XS_STRIDE + k4 * 4,
                       gx + (size_t)t * D_MODEL + k4 * 4);
        }
        CP_COMMIT();
    }

    const int kbase_w = w * KSLICE;            // this warp's k offset in a chunk

    for (int c = 0; c < NCHUNK; ++c) {
        float* cur = (c & 1) ? xs1 : xs0;
        float* nxt = (c & 1) ? xs0 : xs1;

        if (c + 1 < NCHUNK) {
            const float* gsrc = gx + (c + 1) * KCHUNK;
            #pragma unroll
            for (int i = 0; i < 8; ++i) {
                int idx = tid + i * THREADS;
                int t   = idx >> 5;
                int k4  = idx & 31;
                cp_async16(nxt + t * XS_STRIDE + k4 * 4,
                           gsrc + (size_t)t * D_MODEL + k4 * 4);
            }
            CP_COMMIT();
            CP_WAIT(1);                        // chunk c complete
        } else {
            CP_WAIT(0);
        }
        __syncthreads();

        // ---- compute chunk c: warp w covers k in [kbase_w, kbase_w+8)
        #pragma unroll
        for (int g = 0; g < KSLICE / 4; ++g) { // 2 float4 groups
            float4 xv[4];
            #pragma unroll
            for (int t = 0; t < 4; ++t)
                xv[t] = *reinterpret_cast<const float4*>(
                    cur + (lane + t * 32) * XS_STRIDE + kbase_w + g * 4);

            #pragma unroll
            for (int j = 0; j < 4; ++j) {
                int kg = c * KCHUNK + kbase_w + g * 4 + j;      // global k
                u64 wp0 = wt64[kg * 4 + 0];                      // broadcast LDS.64
                u64 wp1 = wt64[kg * 4 + 1];
                u64 wp2 = wt64[kg * 4 + 2];
                u64 wp3 = wt64[kg * 4 + 3];
                #pragma unroll
                for (int t = 0; t < 4; ++t) {
                    float xk = (j == 0) ? xv[t].x : (j == 1) ? xv[t].y
                             : (j == 2) ? xv[t].z : xv[t].w;
                    u64 xx;
                    asm("mov.b64 %0, {%1, %1};" : "=l"(xx) : "f"(xk));
                    asm("fma.rn.f32x2 %0, %1, %2, %0;" : "+l"(acc[t][0]) : "l"(xx), "l"(wp0));
                    asm("fma.rn.f32x2 %0, %1, %2, %0;" : "+l"(acc[t][1]) : "l"(xx), "l"(wp1));
                    asm("fma.rn.f32x2 %0, %1, %2, %0;" : "+l"(acc[t][2]) : "l"(xx), "l"(wp2));
                    asm("fma.rn.f32x2 %0, %1, %2, %0;" : "+l"(acc[t][3]) : "l"(xx), "l"(wp3));
                }
            }
        }
        __syncthreads();   // before nxt buffer gets overwritten in c+2's prefetch
    }

    // ---- cross-warp reduction (reuse xs region: 16*128*4 float2 = 64 KB)
    float2* red = reinterpret_cast<float2*>(xs0);
    #pragma unroll
    for (int t = 0; t < 4; ++t) {
        int tok = lane + t * 32;
        #pragma unroll
        for (int p = 0; p < 4; ++p) {
            float lo, hi;
            asm("mov.b64 {%0, %1}, %2;" : "=f"(lo), "=f"(hi) : "l"(acc[t][p]));
            red[(w * NTOK + tok) * 4 + p] = make_float2(lo, hi);
        }
    }
    __syncthreads();

    float* lgs = xs0 + NWARP * NTOK * 4 * 2;    // 128*8 floats, after red
    {
        int tok = tid >> 2;                     // 0..127
        int p   = tid & 3;
        float2 s = make_float2(0.f, 0.f);
        #pragma unroll
        for (int ww = 0; ww < NWARP; ++ww) {
            float2 v = red[(ww * NTOK + tok) * 4 + p];
            s.x += v.x; s.y += v.y;
        }
        s.x += b[2 * p];
        s.y += b[2 * p + 1];
        reinterpret_cast<float2*>(lgs)[tok * 4 + p] = s;
    }
    __syncthreads();

    // ---- per-token softmax + stable top2 (threads 0..127)
    if (tid < NTOK) {
        const int g = tokenBase + tid;
        float gv[NEXP];
        float mx = -INFINITY;
        #pragma unroll
        for (int e = 0; e < NEXP; ++e) {
            gv[e] = lgs[tid * NEXP + e];
            mx = fmaxf(mx, gv[e]);
        }
        float ssum = 0.f;
        #pragma unroll
        for (int e = 0; e < NEXP; ++e) {
            gv[e] = __expf(gv[e] - mx);
            ssum += gv[e];
        }
        float inv = 1.f / ssum;
        #pragma unroll
        for (int e = 0; e < NEXP; ++e) gv[e] *= inv;

        float* gate_out = out + (size_t)n_tok * 4;
        float4 g0 = make_float4(gv[0], gv[1], gv[2], gv[3]);
        float4 g1 = make_float4(gv[4], gv[5], gv[6], gv[7]);
        *reinterpret_cast<float4*>(gate_out + (size_t)g * NEXP)     = g0;
        *reinterpret_cast<float4*>(gate_out + (size_t)g * NEXP + 4) = g1;

        int i1 = 0; float v1 = gv[0];
        #pragma unroll
        for (int e = 1; e < NEXP; ++e)
            if (gv[e] > v1) { v1 = gv[e]; i1 = e; }
        int i2 = -1; float v2 = -INFINITY;
        #pragma unroll
        for (int e = 0; e < NEXP; ++e)
            if (e != i1 && gv[e] > v2) { v2 = gv[e]; i2 = e; }

        out[(size_t)g * 2 + 0] = v1;
        out[(size_t)g * 2 + 1] = v2;
        float* idx_out = out + (size_t)n_tok * 2;
        idx_out[(size_t)g * 2 + 0] = (float)i1;
        idx_out[(size_t)g * 2 + 1] = (float)i2;
    }
}

extern "C" void kernel_launch(void* const* d_in, const int* in_sizes, int n_in,
                              void* d_out, int out_size)
{
    const float* x = (const float*)d_in[0];
    const float* W = (const float*)d_in[1];
    const float* b = (const float*)d_in[2];
    float* out = (float*)d_out;

    const int n_tok = in_sizes[0] / D_MODEL;    // 16384
    const int smem_bytes = (D_MODEL * NEXP + 2 * NTOK * XS_STRIDE) * (int)sizeof(float);

    static bool attr_set = false;
    if (!attr_set) {
        cudaFuncSetAttribute(top2_router_kernel,
                             cudaFuncAttributeMaxDynamicSharedMemorySize, smem_bytes);
        attr_set = true;
    }

    int blocks = n_tok / NTOK;                  // 128
    top2_router_kernel<<<blocks, THREADS, smem_bytes>>>(x, W, b, out, n_tok);
}

// round 4
// speedup vs baseline: 1.7167x; 1.0255x over previous
#include <cuda_runtime.h>
#include <math.h>

// Top2Router: x[16384,2048] fp32, W[8,2048], b[8]
// out (fp32 concat): top2_val[N*2] | top2_idx[N*2] | gate[N*8]
//
// grid = #SMs, balanced contiguous token ranges (multiples of 8, <=112).
// 4-stage cp.async ring (KCHUNK=64, prefetch distance 2), one bar/chunk.
// XS_STRIDE=68: 272B rows -> 16B-aligned cp.async dsts AND conflict-free
// phased LDS.128 (68 mod 32 == 4). W staged k-major in smem, broadcast
// LDS.64 pairs; f32x2 packed accumulation (FFMA2).

#define D_MODEL   2048
#define NEXP      8
#define NTOKMAX   128
#define KCHUNK    64
#define NCHUNK    (D_MODEL / KCHUNK)   // 32
#define XS_STRIDE 68
#define NSTAGE    4
#define THREADS   512
#define NWARP     16
#define KSLICE    (KCHUNK / NWARP)     // 4 k per warp per chunk

typedef unsigned long long u64;

__device__ __forceinline__ void cp_async16(float* smem_dst, const float* gsrc) {
    unsigned saddr = (unsigned)__cvta_generic_to_shared(smem_dst);
    asm volatile("cp.async.cg.shared.global [%0], [%1], 16;\n"
                 :: "r"(saddr), "l"(gsrc));
}
#define CP_COMMIT() asm volatile("cp.async.commit_group;\n" ::: "memory")
#define CP_WAIT(n)  asm volatile("cp.async.wait_group %0;\n" :: "n"(n) : "memory")

__global__ __launch_bounds__(THREADS, 1)
void top2_router_kernel(const float* __restrict__ x,
                        const float* __restrict__ W,
                        const float* __restrict__ b,
                        float* __restrict__ out,
                        int n_tok)
{
    extern __shared__ float smem[];
    float* wt   = smem;                         // 2048*8 = 16384 floats (64KB)
    float* ring = wt + D_MODEL * NEXP;          // 4 * 128*68 = 34816 floats

    const int tid  = threadIdx.x;
    const int w    = tid >> 5;
    const int lane = tid & 31;

    // balanced token range (units of 8 tokens)
    const int G     = gridDim.x;
    const int units = n_tok >> 3;
    const int s8    = (int)(((long long)blockIdx.x       * units) / G);
    const int e8    = (int)(((long long)(blockIdx.x + 1) * units) / G);
    const int tokenBase = s8 * 8;
    const int ntok_b    = (e8 - s8) * 8;        // <= 112 for G >= 152

    // ---- stage W transposed: wt[k*8+e] = W[e*2048+k]
    #pragma unroll
    for (int i = 0; i < (D_MODEL * NEXP) / THREADS; ++i) {   // 32
        int idx = tid + i * THREADS;
        int e = idx >> 11;
        int k = idx & (D_MODEL - 1);
        wt[k * NEXP + e] = W[idx];
    }
    const u64* wt64 = reinterpret_cast<const u64*>(wt);

    u64 acc[4][4];
    #pragma unroll
    for (int t = 0; t < 4; ++t)
        #pragma unroll
        for (int p = 0; p < 4; ++p) acc[t][p] = 0ull;

    const float* gx = x + (size_t)tokenBase * D_MODEL;

    // chunk tile: ntok_b x 64 floats = up to 2048 float4; 512 thr -> 4 each
    #define PREFETCH(c_) do {                                              \
        float* dst = ring + ((c_) % NSTAGE) * (NTOKMAX * XS_STRIDE);       \
        const float* gsrc = gx + (c_) * KCHUNK;                            \
        _Pragma("unroll")                                                  \
        for (int i = 0; i < 4; ++i) {                                      \
            int idx = tid + i * THREADS;   /* 0..2047 float4 units */      \
            int t   = idx >> 4;            /* 16 float4 per row */         \
            int k4  = idx & 15;                                            \
            if (t < ntok_b)                                                \
                cp_async16(dst + t * XS_STRIDE + k4 * 4,                   \
                           gsrc + (size_t)t * D_MODEL + k4 * 4);           \
        }                                                                  \
        CP_COMMIT();                                                       \
    } while (0)

    PREFETCH(0); PREFETCH(1);

    for (int c = 0; c < NCHUNK; ++c) {
        if (c + 2 < NCHUNK) { PREFETCH(c + 2); CP_WAIT(2); }
        else if (c + 1 < NCHUNK) CP_WAIT(1);
        else                     CP_WAIT(0);
        __syncthreads();

        const float* cur = ring + (c % NSTAGE) * (NTOKMAX * XS_STRIDE);

        // warp w covers k_local in [w*4, w*4+4); thread: tokens lane+t*32
        float4 xv[4];
        #pragma unroll
        for (int t = 0; t < 4; ++t)
            xv[t] = *reinterpret_cast<const float4*>(
                cur + (lane + t * 32) * XS_STRIDE + w * KSLICE);

        #pragma unroll
        for (int j = 0; j < KSLICE; ++j) {
            int kg = c * KCHUNK + w * KSLICE + j;
            u64 wp0 = wt64[kg * 4 + 0];   // broadcast LDS.64
            u64 wp1 = wt64[kg * 4 + 1];
            u64 wp2 = wt64[kg * 4 + 2];
            u64 wp3 = wt64[kg * 4 + 3];
            #pragma unroll
            for (int t = 0; t < 4; ++t) {
                float xk = (j == 0) ? xv[t].x : (j == 1) ? xv[t].y
                         : (j == 2) ? xv[t].z : xv[t].w;
                u64 xx;
                asm("mov.b64 %0, {%1, %1};" : "=l"(xx) : "f"(xk));
                asm("fma.rn.f32x2 %0, %1, %2, %0;" : "+l"(acc[t][0]) : "l"(xx), "l"(wp0));
                asm("fma.rn.f32x2 %0, %1, %2, %0;" : "+l"(acc[t][1]) : "l"(xx), "l"(wp1));
                asm("fma.rn.f32x2 %0, %1, %2, %0;" : "+l"(acc[t][2]) : "l"(xx), "l"(wp2));
                asm("fma.rn.f32x2 %0, %1, %2, %0;" : "+l"(acc[t][3]) : "l"(xx), "l"(wp3));
            }
        }
    }
    __syncthreads();

    // ---- cross-warp reduction (reuse ring: 16*128*4 float2 = 16384 floats)
    float2* red = reinterpret_cast<float2*>(ring);
    #pragma unroll
    for (int t = 0; t < 4; ++t) {
        int tok = lane + t * 32;
        #pragma unroll
        for (int p = 0; p < 4; ++p) {
            float lo, hi;
            asm("mov.b64 {%0, %1}, %2;" : "=f"(lo), "=f"(hi) : "l"(acc[t][p]));
            red[(w * NTOKMAX + tok) * 4 + p] = make_float2(lo, hi);
        }
    }
    __syncthreads();

    float* lgs = ring + NWARP * NTOKMAX * 4 * 2;     // 128*8 floats
    {
        int tok = tid >> 2;                          // 0..127
        int p   = tid & 3;
        float2 s = make_float2(0.f, 0.f);
        #pragma unroll
        for (int ww = 0; ww < NWARP; ++ww) {
            float2 v = red[(ww * NTOKMAX + tok) * 4 + p];
            s.x += v.x; s.y += v.y;
        }
        s.x += b[2 * p];
        s.y += b[2 * p + 1];
        reinterpret_cast<float2*>(lgs)[tok * 4 + p] = s;
    }
    __syncthreads();

    // ---- per-token softmax + stable top2
    if (tid < ntok_b) {
        const int g = tokenBase + tid;
        float gv[NEXP];
        float mx = -INFINITY;
        #pragma unroll
        for (int e = 0; e < NEXP; ++e) {
            gv[e] = lgs[tid * NEXP + e];
            mx = fmaxf(mx, gv[e]);
        }
        float ssum = 0.f;
        #pragma unroll
        for (int e = 0; e < NEXP; ++e) {
            gv[e] = __expf(gv[e] - mx);
            ssum += gv[e];
        }
        float inv = 1.f / ssum;
        #pragma unroll
        for (int e = 0; e < NEXP; ++e) gv[e] *= inv;

        float* gate_out = out + (size_t)n_tok * 4;
        float4 g0 = make_float4(gv[0], gv[1], gv[2], gv[3]);
        float4 g1 = make_float4(gv[4], gv[5], gv[6], gv[7]);
        *reinterpret_cast<float4*>(gate_out + (size_t)g * NEXP)     = g0;
        *reinterpret_cast<float4*>(gate_out + (size_t)g * NEXP + 4) = g1;

        int i1 = 0; float v1 = gv[0];
        #pragma unroll
        for (int e = 1; e < NEXP; ++e)
            if (gv[e] > v1) { v1 = gv[e]; i1 = e; }
        int i2 = -1; float v2 = -INFINITY;
        #pragma unroll
        for (int e = 0; e < NEXP; ++e)
            if (e != i1 && gv[e] > v2) { v2 = gv[e]; i2 = e; }

        out[(size_t)g * 2 + 0] = v1;
        out[(size_t)g * 2 + 1] = v2;
        float* idx_out = out + (size_t)n_tok * 2;
        idx_out[(size_t)g * 2 + 0] = (float)i1;
        idx_out[(size_t)g * 2 + 1] = (float)i2;
    }
}

extern "C" void kernel_launch(void* const* d_in, const int* in_sizes, int n_in,
                              void* d_out, int out_size)
{
    const float* x = (const float*)d_in[0];
    const float* W = (const float*)d_in[1];
    const float* b = (const float*)d_in[2];
    float* out = (float*)d_out;

    const int n_tok = in_sizes[0] / D_MODEL;    // 16384
    const int smem_bytes = (D_MODEL * NEXP + NSTAGE * NTOKMAX * XS_STRIDE)
                           * (int)sizeof(float);  // 204800 B

    static int nsm = 0;
    if (nsm == 0) {
        cudaDeviceProp prop;
        cudaGetDeviceProperties(&prop, 0);
        nsm = prop.multiProcessorCount;          // 152 on GB300
        cudaFuncSetAttribute(top2_router_kernel,
                             cudaFuncAttributeMaxDynamicSharedMemorySize, smem_bytes);
    }

    top2_router_kernel<<<nsm, THREADS, smem_bytes>>>(x, W, b, out, n_tok);
}